// round 12
// baseline (speedup 1.0000x reference)
#include <cuda_runtime.h>
#include <cstdint>

#define L1LEN 512
#define L2LEN 512
#define DDIM  256
#define BATCH 2
#define NG    16
#define GS    16
#define TI    8
#define TJ    32           // source rows per tile
#define JSPLIT 4           // CTAs per i-tile along j
#define NHALF (L2LEN / JSPLIT / TJ)   // tiles per CTA = 4
#define KSTR  256          // V row stride (floats)
#define NSTR  20           // sc2 inner stride
#define NTHR  256

__device__ float g_Q[BATCH * L1LEN * DDIM];
__device__ float g_K[BATCH * L2LEN * DDIM];
__device__ float g_V[BATCH * L2LEN * DDIM];
__device__ float g_pacc[BATCH * 64 * JSPLIT * TI * DDIM];   // partial outputs
__device__ float g_pl[BATCH * 64 * JSPLIT * TI * NG];       // partial exp-sums

// ---------------------------------------------------------------------------
// f32x2 packed helpers (Blackwell): FFMA2 / FADD2 via PTX
// ---------------------------------------------------------------------------
__device__ __forceinline__ unsigned long long fma2u(unsigned long long a,
                                                    unsigned long long b,
                                                    unsigned long long c) {
    unsigned long long r;
    asm("fma.rn.f32x2 %0, %1, %2, %3;" : "=l"(r) : "l"(a), "l"(b), "l"(c));
    return r;
}

// acc += relu(q2 + nk2) * w2   (elementwise packed; relu on scalar halves)
__device__ __forceinline__ void relu_fma(unsigned long long& acc,
                                         unsigned long long q2,
                                         unsigned long long nk2,
                                         unsigned long long w2) {
    asm("{\n\t"
        ".reg .b64 d;\n\t"
        ".reg .f32 lo, hi;\n\t"
        "add.rn.f32x2 d, %1, %2;\n\t"
        "mov.b64 {lo, hi}, d;\n\t"
        "max.f32 lo, lo, 0f00000000;\n\t"
        "max.f32 hi, hi, 0f00000000;\n\t"
        "mov.b64 d, {lo, hi};\n\t"
        "fma.rn.f32x2 %0, d, %3, %0;\n\t"
        "}"
        : "+l"(acc) : "l"(q2), "l"(nk2), "l"(w2));
}

__device__ __forceinline__ unsigned long long pk2(float a, float b) {
    unsigned long long r;
    asm("mov.b64 %0, {%1, %2};" : "=l"(r) : "f"(a), "f"(b));
    return r;
}

__device__ __forceinline__ float2 upk2(unsigned long long v) {
    float2 r;
    asm("mov.b64 {%0, %1}, %2;" : "=f"(r.x), "=f"(r.y) : "l"(v));
    return r;
}

// ---------------------------------------------------------------------------
// QKV projection via tensor cores, 3xTF32 error-compensated (unchanged).
// ---------------------------------------------------------------------------
__device__ __forceinline__ uint32_t f2tf32(float f) {
    uint32_t r;
    asm("cvt.rna.tf32.f32 %0, %1;" : "=r"(r) : "f"(f));
    return r;
}

__device__ __forceinline__ void mma_tf32(float* c, const uint32_t* a,
                                         uint32_t b0, uint32_t b1) {
    asm("mma.sync.aligned.m16n8k8.row.col.f32.tf32.tf32.f32 "
        "{%0,%1,%2,%3}, {%4,%5,%6,%7}, {%8,%9}, {%0,%1,%2,%3};"
        : "+f"(c[0]), "+f"(c[1]), "+f"(c[2]), "+f"(c[3])
        : "r"(a[0]), "r"(a[1]), "r"(a[2]), "r"(a[3]), "r"(b0), "r"(b1));
}

__global__ __launch_bounds__(128) void qkv_gemm(const float* __restrict__ x_target,
                                                const float* __restrict__ x_source,
                                                const float* __restrict__ Wq,
                                                const float* __restrict__ Wk,
                                                const float* __restrict__ Wv) {
    const int z = blockIdx.z;
    const float* __restrict__ x = (z == 0) ? x_target : x_source;
    const float* __restrict__ W = (z == 0) ? Wq : ((z == 1) ? Wk : Wv);
    float* __restrict__ y       = (z == 0) ? g_Q : ((z == 1) ? g_K : g_V);

    __shared__ float    xs[64][36];
    __shared__ uint32_t wsh[32][36];
    __shared__ uint32_t wsl[32][36];

    const int t    = threadIdx.x;
    const int warp = t >> 5;
    const int lane = t & 31;
    const int gid  = lane >> 2;
    const int tig  = lane & 3;
    const int m_blk = blockIdx.x * 64;
    const int n_blk = blockIdx.y * 32;

    float acc[4][4] = {};

    for (int chunk = 0; chunk < 8; chunk++) {
        const int kc = chunk * 32;
        __syncthreads();
#pragma unroll
        for (int i = 0; i < 4; i++) {
            int idx = t + i * 128;
            int row = idx >> 3, col = (idx & 7) * 4;
            *(float4*)&xs[row][col] =
                *(const float4*)&x[(m_blk + row) * DDIM + kc + col];
        }
#pragma unroll
        for (int i = 0; i < 2; i++) {
            int idx = t + i * 128;
            int row = idx >> 3, col = (idx & 7) * 4;
            float4 wv = *(const float4*)&W[(n_blk + row) * DDIM + kc + col];
            uint32_t h0 = f2tf32(wv.x), h1 = f2tf32(wv.y);
            uint32_t h2 = f2tf32(wv.z), h3 = f2tf32(wv.w);
            wsh[row][col + 0] = h0; wsh[row][col + 1] = h1;
            wsh[row][col + 2] = h2; wsh[row][col + 3] = h3;
            wsl[row][col + 0] = f2tf32(wv.x - __uint_as_float(h0));
            wsl[row][col + 1] = f2tf32(wv.y - __uint_as_float(h1));
            wsl[row][col + 2] = f2tf32(wv.z - __uint_as_float(h2));
            wsl[row][col + 3] = f2tf32(wv.w - __uint_as_float(h3));
        }
        __syncthreads();

#pragma unroll
        for (int ks = 0; ks < 4; ks++) {
            const int k0 = ks * 8;
            float af[4];
            af[0] = xs[warp * 16 + gid][k0 + tig];
            af[1] = xs[warp * 16 + gid + 8][k0 + tig];
            af[2] = xs[warp * 16 + gid][k0 + tig + 4];
            af[3] = xs[warp * 16 + gid + 8][k0 + tig + 4];
            uint32_t ahi[4], alo[4];
#pragma unroll
            for (int j = 0; j < 4; j++) {
                ahi[j] = f2tf32(af[j]);
                alo[j] = f2tf32(af[j] - __uint_as_float(ahi[j]));
            }
#pragma unroll
            for (int nb = 0; nb < 4; nb++) {
                uint32_t bhi0 = wsh[nb * 8 + gid][k0 + tig];
                uint32_t bhi1 = wsh[nb * 8 + gid][k0 + tig + 4];
                uint32_t blo0 = wsl[nb * 8 + gid][k0 + tig];
                uint32_t blo1 = wsl[nb * 8 + gid][k0 + tig + 4];
                mma_tf32(acc[nb], ahi, bhi0, bhi1);
                mma_tf32(acc[nb], ahi, blo0, blo1);
                mma_tf32(acc[nb], alo, bhi0, bhi1);
            }
        }
    }

    const int m = m_blk + warp * 16 + gid;
#pragma unroll
    for (int nb = 0; nb < 4; nb++) {
        const int n = n_blk + nb * 8 + 2 * tig;
        *(float2*)&y[m * DDIM + n]       = make_float2(acc[nb][0], acc[nb][1]);
        *(float2*)&y[(m + 8) * DDIM + n] = make_float2(acc[nb][2], acc[nb][3]);
    }
}

// ---------------------------------------------------------------------------
// Fused attention, f32x2-packed math, 4-way j-split, no-max softmax.
// 256 threads, 3 CTAs/SM. Grid 512 = BATCH * 64 * JSPLIT.
//   B: thread (jj, nc): packed relu-fma scores, 8 i x 2 groups -> sc2 (exp'd)
//   D: warp (ih, jq): 4 i-rows x 8 j x 256 d, FFMA2 accumulate
// ---------------------------------------------------------------------------
__global__ __launch_bounds__(NTHR, 3) void attn_kernel(const float* __restrict__ wmlp,
                                                       const float* __restrict__ bmlp) {
    extern __shared__ float sm[];
    float* q   = sm;                        // 2048
    float* vt  = q + TI * DDIM;             // 32*256 = 8192 (reused as scratch)
    float* sc2 = vt + TJ * KSTR;            // 8*32*20 = 5120  [(i*TJ+j)*NSTR + n]

    const int t     = threadIdx.x;
    const int bx    = blockIdx.x;
    const int b     = bx >> 8;              // / (64*JSPLIT)
    const int itile = (bx >> 2) & 63;
    const int jh2   = bx & 3;               // j quarter of L2: 128 rows
    const int i_base = itile * TI;
    const int part   = bx;

    const int jj = t & 31;
    const int nc = t >> 5;                  // 0..7 -> groups 2nc, 2nc+1
    const int qp = t & 31;
    const int ih = (t >> 5) & 1;            // i rows 4*ih .. 4*ih+3
    const int jq = t >> 6;                  // j quarter of tile (8 j each)
    const int n0 = (4 * qp) & 15;

    const float b0 = bmlp[0];
    unsigned long long w2[8];
#pragma unroll
    for (int p = 0; p < 8; p++) w2[p] = pk2(wmlp[2 * p], wmlp[2 * p + 1]);

    {
        const float* Qg = g_Q + (b * L1LEN + i_base) * DDIM;
#pragma unroll
        for (int it = 0; it < 2; it++) {
            int idx = t + it * NTHR;
            int row = idx >> 6, col = (idx & 63) * 4;
            *(float4*)&q[row * DDIM + col] = *(const float4*)&Qg[row * DDIM + col];
        }
    }

    ulonglong2 acc2[4][2];
#pragma unroll
    for (int r = 0; r < 4; r++) {
        acc2[r][0].x = 0ull; acc2[r][0].y = 0ull;
        acc2[r][1].x = 0ull; acc2[r][1].y = 0ull;
    }
    float lsum = 0.f;

    for (int tile = 0; tile < NHALF; tile++) {
        __syncthreads();
        const int j_glob = jh2 * (L2LEN / JSPLIT) + tile * TJ;
        // ---- Phase A: stage V tile (overlaps with B; no barrier between)
        {
            const float* Vg = g_V + (b * L2LEN + j_glob) * DDIM;
#pragma unroll
            for (int it = 0; it < (TJ * DDIM / 4) / NTHR; it++) {
                int idx = t + it * NTHR;
                int row = idx >> 6, col = (idx & 63) * 4;
                *(float4*)&vt[row * KSTR + col] = *(const float4*)&Vg[row * DDIM + col];
            }
        }

        // ---- Phase B: packed scores + exp -> sc2
#pragma unroll
        for (int n2 = 0; n2 < 2; n2++) {
            const int n = nc * 2 + n2;
            const float* kr = g_K + (b * L2LEN + j_glob + jj) * DDIM + n * GS;
            unsigned long long nk2[8];
#pragma unroll
            for (int dq = 0; dq < 4; dq++) {
                float4 kq = *(const float4*)&kr[dq * 4];
                nk2[dq * 2]     = pk2(-kq.x, -kq.y);
                nk2[dq * 2 + 1] = pk2(-kq.z, -kq.w);
            }
            unsigned long long s2[8];
#pragma unroll
            for (int i = 0; i < 8; i++) s2[i] = 0ull;
#pragma unroll
            for (int dq = 0; dq < 4; dq++) {
#pragma unroll
                for (int i = 0; i < 8; i++) {
                    const ulonglong2 qv =
                        *(const ulonglong2*)&q[i * DDIM + n * GS + dq * 4];
                    relu_fma(s2[i], qv.x, nk2[dq * 2], w2[dq * 2]);
                    relu_fma(s2[i], qv.y, nk2[dq * 2 + 1], w2[dq * 2 + 1]);
                }
            }
#pragma unroll
            for (int i = 0; i < 8; i++) {
                float2 f = upk2(s2[i]);
                sc2[(i * TJ + jj) * NSTR + n] =
                    __expf(fmaxf(f.x + f.y + b0, 0.f));
            }
        }
        __syncthreads();

        // ---- exp-sum (t<128, overlaps with D)
        if (t < TI * NG) {
            const int ci = t >> 4, cn = t & 15;
            const float* base = sc2 + ci * TJ * NSTR + cn;
            float s0 = 0.f, s1 = 0.f;
#pragma unroll
            for (int j = 0; j < TJ; j += 2) {
                s0 += base[j * NSTR];
                s1 += base[(j + 1) * NSTR];
            }
            lsum += s0 + s1;
        }

        // ---- Phase D: FFMA2 accumulate; warp (ih,jq): 4 i x 8 j x 256 d
        {
            const int j0 = jq * 8;
#pragma unroll
            for (int jo = 0; jo < 8; jo++) {
                const int j = j0 + jo;
                const ulonglong2 v0 = *(const ulonglong2*)&vt[j * KSTR + 4 * qp];
                const ulonglong2 v1 =
                    *(const ulonglong2*)&vt[j * KSTR + 4 * qp + 128];
#pragma unroll
                for (int r = 0; r < 4; r++) {
                    const ulonglong2 p = *(const ulonglong2*)
                        &sc2[((4 * ih + r) * TJ + j) * NSTR + n0];
                    acc2[r][0].x = fma2u(p.x, v0.x, acc2[r][0].x);
                    acc2[r][0].y = fma2u(p.y, v0.y, acc2[r][0].y);
                    acc2[r][1].x = fma2u(p.x, v1.x, acc2[r][1].x);
                    acc2[r][1].y = fma2u(p.y, v1.y, acc2[r][1].y);
                }
            }
        }
    }

    // ---- reduce jq partials via vt scratch, write partials to global
    __syncthreads();
    {
        float* scr = vt;   // warp w slot: w*1024 + qp*32 + r*8 (+4)
        int base = (t >> 5) * 1024 + qp * 32;
#pragma unroll
        for (int r = 0; r < 4; r++) {
            *(float4*)&scr[base + r * 8]     = *(float4*)&acc2[r][0];
            *(float4*)&scr[base + r * 8 + 4] = *(float4*)&acc2[r][1];
        }
    }
    __syncthreads();
    {
        // thread t owns (i = t>>5, qp = t&31); warp for (ih,jq) = ih + 2*jq
        const int i   = t >> 5;
        const int mih = i >> 2, r = i & 3;
        const float* scr = vt;
        float4 s0 = make_float4(0.f, 0.f, 0.f, 0.f);
        float4 s1 = make_float4(0.f, 0.f, 0.f, 0.f);
#pragma unroll
        for (int jqq = 0; jqq < 4; jqq++) {
            const int wv = mih + 2 * jqq;
            const float* pbase = scr + wv * 1024 + (t & 31) * 32 + r * 8;
            float4 a0 = *(const float4*)&pbase[0];
            float4 a1 = *(const float4*)&pbase[4];
            s0.x += a0.x; s0.y += a0.y; s0.z += a0.z; s0.w += a0.w;
            s1.x += a1.x; s1.y += a1.y; s1.z += a1.z; s1.w += a1.w;
        }
        float* pb = g_pacc + part * (TI * DDIM);
        *(float4*)&pb[i * DDIM + 4 * (t & 31)]       = s0;
        *(float4*)&pb[i * DDIM + 4 * (t & 31) + 128] = s1;
    }
    if (t < TI * NG) g_pl[part * (TI * NG) + t] = lsum;
}

// ---------------------------------------------------------------------------
// Merge: out = sum_p acc_p / sum_p l_p   over JSPLIT partials
// ---------------------------------------------------------------------------
__global__ __launch_bounds__(256) void merge_kernel(float* __restrict__ out) {
    const int bx = blockIdx.x;              // (b*64 + itile)
    const int t  = threadIdx.x;
    float* ob = out + bx * (TI * DDIM);

#pragma unroll
    for (int k = 0; k < 2; k++) {
        int idx = t + k * 256;
        int i   = idx >> 6;
        int d0  = (idx & 63) * 4;
        int nq  = d0 & 15;
        float4 xs = make_float4(0.f, 0.f, 0.f, 0.f);
        float4 us = make_float4(0.f, 0.f, 0.f, 0.f);
#pragma unroll
        for (int p = 0; p < JSPLIT; p++) {
            const float* a = g_pacc + (bx * JSPLIT + p) * (TI * DDIM);
            const float* l = g_pl + (bx * JSPLIT + p) * (TI * NG);
            float4 xv = *(const float4*)&a[i * DDIM + d0];
            float4 uv = *(const float4*)&l[i * NG + nq];
            xs.x += xv.x; xs.y += xv.y; xs.z += xv.z; xs.w += xv.w;
            us.x += uv.x; us.y += uv.y; us.z += uv.z; us.w += uv.w;
        }
        float4 r;
        r.x = xs.x / us.x;
        r.y = xs.y / us.y;
        r.z = xs.z / us.z;
        r.w = xs.w / us.w;
        *(float4*)&ob[i * DDIM + d0] = r;
    }
}

// ---------------------------------------------------------------------------
extern "C" void kernel_launch(void* const* d_in, const int* in_sizes, int n_in,
                              void* d_out, int out_size) {
    const float* x_source = (const float*)d_in[0];
    const float* x_target = (const float*)d_in[1];
    const float* Wq       = (const float*)d_in[2];
    const float* Wk       = (const float*)d_in[3];
    const float* Wv       = (const float*)d_in[4];
    const float* w_mlp    = (const float*)d_in[5];
    const float* b_mlp    = (const float*)d_in[6];
    float* out            = (float*)d_out;

    dim3 ggrid(16, 8, 3);
    qkv_gemm<<<ggrid, 128>>>(x_target, x_source, Wq, Wk, Wv);

    const size_t smem_bytes =
        (TI * DDIM + TJ * KSTR + TI * TJ * NSTR) * sizeof(float);
    cudaFuncSetAttribute(attn_kernel, cudaFuncAttributeMaxDynamicSharedMemorySize,
                         (int)smem_bytes);
    attn_kernel<<<BATCH * 64 * JSPLIT, NTHR, smem_bytes>>>(w_mlp, b_mlp);

    merge_kernel<<<BATCH * 64, 256>>>(out);
}

// round 14
// speedup vs baseline: 1.1166x; 1.1166x over previous
#include <cuda_runtime.h>
#include <cstdint>

#define L1LEN 512
#define L2LEN 512
#define DDIM  256
#define BATCH 2
#define NG    16
#define GS    16
#define TI    8
#define TJ    32           // source rows per tile
#define JSPLIT 2
#define NHALF (L2LEN / JSPLIT / TJ)   // 8 tiles per CTA
#define KSTR  256          // V row stride (floats)
#define NSTR  20           // sc2 inner stride
#define NTHR  256

__device__ float g_Q[BATCH * L1LEN * DDIM];
__device__ float g_K[BATCH * L2LEN * DDIM];
__device__ float g_V[BATCH * L2LEN * DDIM];
__device__ float g_pacc[BATCH * 64 * JSPLIT * TI * DDIM];
__device__ float g_pl[BATCH * 64 * JSPLIT * TI * NG];

// ---------------------------------------------------------------------------
// f32x2 packed helpers
// ---------------------------------------------------------------------------
__device__ __forceinline__ unsigned long long fma2u(unsigned long long a,
                                                    unsigned long long b,
                                                    unsigned long long c) {
    unsigned long long r;
    asm("fma.rn.f32x2 %0, %1, %2, %3;" : "=l"(r) : "l"(a), "l"(b), "l"(c));
    return r;
}

__device__ __forceinline__ void relu_fma(unsigned long long& acc,
                                         unsigned long long q2,
                                         unsigned long long nk2,
                                         unsigned long long w2) {
    asm("{\n\t"
        ".reg .b64 d;\n\t"
        ".reg .f32 lo, hi;\n\t"
        "add.rn.f32x2 d, %1, %2;\n\t"
        "mov.b64 {lo, hi}, d;\n\t"
        "max.f32 lo, lo, 0f00000000;\n\t"
        "max.f32 hi, hi, 0f00000000;\n\t"
        "mov.b64 d, {lo, hi};\n\t"
        "fma.rn.f32x2 %0, d, %3, %0;\n\t"
        "}"
        : "+l"(acc) : "l"(q2), "l"(nk2), "l"(w2));
}

__device__ __forceinline__ unsigned long long pk2(float a, float b) {
    unsigned long long r;
    asm("mov.b64 %0, {%1, %2};" : "=l"(r) : "f"(a), "f"(b));
    return r;
}

__device__ __forceinline__ float2 upk2(unsigned long long v) {
    float2 r;
    asm("mov.b64 {%0, %1}, %2;" : "=f"(r.x), "=f"(r.y) : "l"(v));
    return r;
}

// cp.async 16B + group ops
__device__ __forceinline__ void cp16(uint32_t dst, const void* src) {
    asm volatile("cp.async.cg.shared.global [%0], [%1], 16;"
                 :: "r"(dst), "l"(src));
}
__device__ __forceinline__ void cp_commit() {
    asm volatile("cp.async.commit_group;");
}
__device__ __forceinline__ void cp_wait1() {
    asm volatile("cp.async.wait_group 1;");
}

// ---------------------------------------------------------------------------
// QKV projection via tensor cores, 3xTF32. 32x32 tiles, grid (32,8,3)=768.
// 128 threads: warp = (mh, nh): m16 x n16 subtile, nb loop x2.
// ---------------------------------------------------------------------------
__device__ __forceinline__ uint32_t f2tf32(float f) {
    uint32_t r;
    asm("cvt.rna.tf32.f32 %0, %1;" : "=r"(r) : "f"(f));
    return r;
}

__device__ __forceinline__ void mma_tf32(float* c, const uint32_t* a,
                                         uint32_t b0, uint32_t b1) {
    asm("mma.sync.aligned.m16n8k8.row.col.f32.tf32.tf32.f32 "
        "{%0,%1,%2,%3}, {%4,%5,%6,%7}, {%8,%9}, {%0,%1,%2,%3};"
        : "+f"(c[0]), "+f"(c[1]), "+f"(c[2]), "+f"(c[3])
        : "r"(a[0]), "r"(a[1]), "r"(a[2]), "r"(a[3]), "r"(b0), "r"(b1));
}

__global__ __launch_bounds__(128) void qkv_gemm(const float* __restrict__ x_target,
                                                const float* __restrict__ x_source,
                                                const float* __restrict__ Wq,
                                                const float* __restrict__ Wk,
                                                const float* __restrict__ Wv) {
    const int z = blockIdx.z;
    const float* __restrict__ x = (z == 0) ? x_target : x_source;
    const float* __restrict__ W = (z == 0) ? Wq : ((z == 1) ? Wk : Wv);
    float* __restrict__ y       = (z == 0) ? g_Q : ((z == 1) ? g_K : g_V);

    __shared__ float    xs[32][36];
    __shared__ uint32_t wsh[32][36];
    __shared__ uint32_t wsl[32][36];

    const int t    = threadIdx.x;
    const int warp = t >> 5;
    const int lane = t & 31;
    const int gid  = lane >> 2;
    const int tig  = lane & 3;
    const int mh   = warp & 1;       // m16 half
    const int nh   = warp >> 1;      // n16 half
    const int m_blk = blockIdx.x * 32;
    const int n_blk = blockIdx.y * 32;

    float acc[2][4] = {};

    for (int chunk = 0; chunk < 8; chunk++) {
        const int kc = chunk * 32;
        __syncthreads();
#pragma unroll
        for (int i = 0; i < 2; i++) {
            int idx = t + i * 128;
            int row = idx >> 3, col = (idx & 7) * 4;
            *(float4*)&xs[row][col] =
                *(const float4*)&x[(m_blk + row) * DDIM + kc + col];
        }
#pragma unroll
        for (int i = 0; i < 2; i++) {
            int idx = t + i * 128;
            int row = idx >> 3, col = (idx & 7) * 4;
            float4 wv = *(const float4*)&W[(n_blk + row) * DDIM + kc + col];
            uint32_t h0 = f2tf32(wv.x), h1 = f2tf32(wv.y);
            uint32_t h2 = f2tf32(wv.z), h3 = f2tf32(wv.w);
            wsh[row][col + 0] = h0; wsh[row][col + 1] = h1;
            wsh[row][col + 2] = h2; wsh[row][col + 3] = h3;
            wsl[row][col + 0] = f2tf32(wv.x - __uint_as_float(h0));
            wsl[row][col + 1] = f2tf32(wv.y - __uint_as_float(h1));
            wsl[row][col + 2] = f2tf32(wv.z - __uint_as_float(h2));
            wsl[row][col + 3] = f2tf32(wv.w - __uint_as_float(h3));
        }
        __syncthreads();

#pragma unroll
        for (int ks = 0; ks < 4; ks++) {
            const int k0 = ks * 8;
            float af[4];
            af[0] = xs[mh * 16 + gid][k0 + tig];
            af[1] = xs[mh * 16 + gid + 8][k0 + tig];
            af[2] = xs[mh * 16 + gid][k0 + tig + 4];
            af[3] = xs[mh * 16 + gid + 8][k0 + tig + 4];
            uint32_t ahi[4], alo[4];
#pragma unroll
            for (int j = 0; j < 4; j++) {
                ahi[j] = f2tf32(af[j]);
                alo[j] = f2tf32(af[j] - __uint_as_float(ahi[j]));
            }
#pragma unroll
            for (int nb = 0; nb < 2; nb++) {
                const int nrow = nh * 16 + nb * 8 + gid;
                uint32_t bhi0 = wsh[nrow][k0 + tig];
                uint32_t bhi1 = wsh[nrow][k0 + tig + 4];
                uint32_t blo0 = wsl[nrow][k0 + tig];
                uint32_t blo1 = wsl[nrow][k0 + tig + 4];
                mma_tf32(acc[nb], ahi, bhi0, bhi1);
                mma_tf32(acc[nb], ahi, blo0, blo1);
                mma_tf32(acc[nb], alo, bhi0, bhi1);
            }
        }
    }

    const int m = m_blk + mh * 16 + gid;
#pragma unroll
    for (int nb = 0; nb < 2; nb++) {
        const int n = n_blk + nh * 16 + nb * 8 + 2 * tig;
        *(float2*)&y[m * DDIM + n]       = make_float2(acc[nb][0], acc[nb][1]);
        *(float2*)&y[(m + 8) * DDIM + n] = make_float2(acc[nb][2], acc[nb][3]);
    }
}

// ---------------------------------------------------------------------------
// Fused attention, f32x2 math, 2-way j-split, cp.async double-buffered V.
// 256 threads, 2 CTAs/SM. Grid 256 = BATCH * 64 * 2.
// ---------------------------------------------------------------------------
__global__ __launch_bounds__(NTHR, 2) void attn_kernel(const float* __restrict__ wmlp,
                                                       const float* __restrict__ bmlp) {
    extern __shared__ float sm[];
    float* q    = sm;                       // 2048 floats
    float* vbuf = q + TI * DDIM;            // 2 x 8192 floats
    float* sc2  = vbuf + 2 * TJ * KSTR;     // 5120 floats [(i*TJ+j)*NSTR + n]

    const int t     = threadIdx.x;
    const int bx    = blockIdx.x;
    const int b     = bx >> 7;
    const int itile = (bx >> 1) & 63;
    const int jh2   = bx & 1;               // j half of L2 (256 rows)
    const int i_base = itile * TI;
    const int part   = bx;

    const int jj = t & 31;
    const int nc = t >> 5;                  // groups 2nc, 2nc+1
    const int qp = t & 31;
    const int ih = (t >> 5) & 1;
    const int jq = t >> 6;
    const int n0 = (4 * qp) & 15;

    const float b0 = bmlp[0];
    unsigned long long w2[8];
#pragma unroll
    for (int p = 0; p < 8; p++) w2[p] = pk2(wmlp[2 * p], wmlp[2 * p + 1]);

    {
        const float* Qg = g_Q + (b * L1LEN + i_base) * DDIM;
#pragma unroll
        for (int it = 0; it < 2; it++) {
            int idx = t + it * NTHR;
            int row = idx >> 6, col = (idx & 63) * 4;
            *(float4*)&q[row * DDIM + col] = *(const float4*)&Qg[row * DDIM + col];
        }
    }

    const float* Vg = g_V + (b * L2LEN + jh2 * (L2LEN / JSPLIT)) * DDIM;
    // prologue: prefetch FULL V tile 0 (32 rows = 8 float4 per thread)
    {
        uint32_t dst = (uint32_t)__cvta_generic_to_shared(vbuf);
#pragma unroll
        for (int it = 0; it < (TJ * DDIM / 4) / NTHR; it++) {
            int idx = t + it * NTHR;
            int row = idx >> 6, col = (idx & 63) * 4;
            cp16(dst + (row * KSTR + col) * 4, &Vg[row * DDIM + col]);
        }
        cp_commit();
    }

    ulonglong2 acc2[4][2];
#pragma unroll
    for (int r = 0; r < 4; r++) {
        acc2[r][0].x = 0ull; acc2[r][0].y = 0ull;
        acc2[r][1].x = 0ull; acc2[r][1].y = 0ull;
    }
    float lsum = 0.f;

    for (int tile = 0; tile < NHALF; tile++) {
        __syncthreads();   // prev D done with vbuf[(tile+1)&1] and sc2
        // prefetch FULL V(tile+1) into the buffer prev D just released
        if (tile + 1 < NHALF) {
            const float* Vn = Vg + (tile + 1) * TJ * DDIM;
            uint32_t dst = (uint32_t)__cvta_generic_to_shared(
                vbuf + ((tile + 1) & 1) * TJ * KSTR);
#pragma unroll
            for (int it = 0; it < (TJ * DDIM / 4) / NTHR; it++) {
                int idx = t + it * NTHR;
                int row = idx >> 6, col = (idx & 63) * 4;
                cp16(dst + (row * KSTR + col) * 4, &Vn[row * DDIM + col]);
            }
        }
        cp_commit();       // one group per iteration (possibly empty)

        const int j_glob = jh2 * (L2LEN / JSPLIT) + tile * TJ;
        // ---- Phase B: packed scores + exp -> sc2
#pragma unroll
        for (int n2 = 0; n2 < 2; n2++) {
            const int n = nc * 2 + n2;
            const float* kr = g_K + (b * L2LEN + j_glob + jj) * DDIM + n * GS;
            unsigned long long nk2[8];
#pragma unroll
            for (int dq = 0; dq < 4; dq++) {
                float4 kq = *(const float4*)&kr[dq * 4];
                nk2[dq * 2]     = pk2(-kq.x, -kq.y);
                nk2[dq * 2 + 1] = pk2(-kq.z, -kq.w);
            }
            unsigned long long s2[8];
#pragma unroll
            for (int i = 0; i < 8; i++) s2[i] = 0ull;
#pragma unroll
            for (int dq = 0; dq < 4; dq++) {
#pragma unroll
                for (int i = 0; i < 8; i++) {
                    const ulonglong2 qv =
                        *(const ulonglong2*)&q[i * DDIM + n * GS + dq * 4];
                    relu_fma(s2[i], qv.x, nk2[dq * 2], w2[dq * 2]);
                    relu_fma(s2[i], qv.y, nk2[dq * 2 + 1], w2[dq * 2 + 1]);
                }
            }
#pragma unroll
            for (int i = 0; i < 8; i++) {
                float2 f = upk2(s2[i]);
                sc2[(i * TJ + jj) * NSTR + n] =
                    __expf(fmaxf(f.x + f.y + b0, 0.f));
            }
        }
        cp_wait1();        // V(tile) delivered (V(tile+1) may still fly)
        __syncthreads();   // sc2 + V(tile) visible to all

        const float* vt = vbuf + (tile & 1) * TJ * KSTR;

        // ---- exp-sum (t<128, overlaps with D)
        if (t < TI * NG) {
            const int ci = t >> 4, cn = t & 15;
            const float* base = sc2 + ci * TJ * NSTR + cn;
            float s0 = 0.f, s1 = 0.f;
#pragma unroll
            for (int j = 0; j < TJ; j += 2) {
                s0 += base[j * NSTR];
                s1 += base[(j + 1) * NSTR];
            }
            lsum += s0 + s1;
        }

        // ---- Phase D: FFMA2 accumulate; warp (ih,jq): 4 i x 8 j x 256 d
        {
            const int j0 = jq * 8;
#pragma unroll
            for (int jo = 0; jo < 8; jo++) {
                const int j = j0 + jo;
                const ulonglong2 v0 = *(const ulonglong2*)&vt[j * KSTR + 4 * qp];
                const ulonglong2 v1 =
                    *(const ulonglong2*)&vt[j * KSTR + 4 * qp + 128];
#pragma unroll
                for (int r = 0; r < 4; r++) {
                    const ulonglong2 p = *(const ulonglong2*)
                        &sc2[((4 * ih + r) * TJ + j) * NSTR + n0];
                    acc2[r][0].x = fma2u(p.x, v0.x, acc2[r][0].x);
                    acc2[r][0].y = fma2u(p.y, v0.y, acc2[r][0].y);
                    acc2[r][1].x = fma2u(p.x, v1.x, acc2[r][1].x);
                    acc2[r][1].y = fma2u(p.y, v1.y, acc2[r][1].y);
                }
            }
        }
    }

    // ---- reduce jq partials via vbuf scratch, write partials to global
    __syncthreads();
    {
        float* scr = vbuf;
        int base = (t >> 5) * 1024 + qp * 32;
#pragma unroll
        for (int r = 0; r < 4; r++) {
            *(float4*)&scr[base + r * 8]     = *(float4*)&acc2[r][0];
            *(float4*)&scr[base + r * 8 + 4] = *(float4*)&acc2[r][1];
        }
    }
    __syncthreads();
    {
        const int i   = t >> 5;
        const int mih = i >> 2, r = i & 3;
        const float* scr = vbuf;
        float4 s0 = make_float4(0.f, 0.f, 0.f, 0.f);
        float4 s1 = make_float4(0.f, 0.f, 0.f, 0.f);
#pragma unroll
        for (int jqq = 0; jqq < 4; jqq++) {
            const int wv = mih + 2 * jqq;
            const float* pbase = scr + wv * 1024 + (t & 31) * 32 + r * 8;
            float4 a0 = *(const float4*)&pbase[0];
            float4 a1 = *(const float4*)&pbase[4];
            s0.x += a0.x; s0.y += a0.y; s0.z += a0.z; s0.w += a0.w;
            s1.x += a1.x; s1.y += a1.y; s1.z += a1.z; s1.w += a1.w;
        }
        float* pb = g_pacc + part * (TI * DDIM);
        *(float4*)&pb[i * DDIM + 4 * (t & 31)]       = s0;
        *(float4*)&pb[i * DDIM + 4 * (t & 31) + 128] = s1;
    }
    if (t < TI * NG) g_pl[part * (TI * NG) + t] = lsum;
}

// ---------------------------------------------------------------------------
// Merge: out = (acc0 + acc1) / (l0 + l1)
// ---------------------------------------------------------------------------
__global__ __launch_bounds__(256) void merge_kernel(float* __restrict__ out) {
    const int bx = blockIdx.x;
    const int t  = threadIdx.x;
    const int p0 = bx * 2, p1 = bx * 2 + 1;
    const float* a0 = g_pacc + p0 * (TI * DDIM);
    const float* a1 = g_pacc + p1 * (TI * DDIM);
    const float* l0 = g_pl + p0 * (TI * NG);
    const float* l1 = g_pl + p1 * (TI * NG);
    float* ob = out + bx * (TI * DDIM);

#pragma unroll
    for (int k = 0; k < 2; k++) {
        int idx = t + k * 256;
        int i   = idx >> 6;
        int d0  = (idx & 63) * 4;
        int nq  = d0 & 15;
        float4 x0 = *(const float4*)&a0[i * DDIM + d0];
        float4 x1 = *(const float4*)&a1[i * DDIM + d0];
        float4 u0 = *(const float4*)&l0[i * NG + nq];
        float4 u1 = *(const float4*)&l1[i * NG + nq];
        float4 r;
        r.x = (x0.x + x1.x) / (u0.x + u1.x);
        r.y = (x0.y + x1.y) / (u0.y + u1.y);
        r.z = (x0.z + x1.z) / (u0.z + u1.z);
        r.w = (x0.w + x1.w) / (u0.w + u1.w);
        *(float4*)&ob[i * DDIM + d0] = r;
    }
}

// ---------------------------------------------------------------------------
extern "C" void kernel_launch(void* const* d_in, const int* in_sizes, int n_in,
                              void* d_out, int out_size) {
    const float* x_source = (const float*)d_in[0];
    const float* x_target = (const float*)d_in[1];
    const float* Wq       = (const float*)d_in[2];
    const float* Wk       = (const float*)d_in[3];
    const float* Wv       = (const float*)d_in[4];
    const float* w_mlp    = (const float*)d_in[5];
    const float* b_mlp    = (const float*)d_in[6];
    float* out            = (float*)d_out;

    dim3 ggrid(32, 8, 3);
    qkv_gemm<<<ggrid, 128>>>(x_target, x_source, Wq, Wk, Wv);

    const size_t smem_bytes =
        (TI * DDIM + 2 * TJ * KSTR + TI * TJ * NSTR) * sizeof(float);
    cudaFuncSetAttribute(attn_kernel, cudaFuncAttributeMaxDynamicSharedMemorySize,
                         (int)smem_bytes);
    attn_kernel<<<BATCH * 64 * JSPLIT, NTHR, smem_bytes>>>(w_mlp, b_mlp);

    merge_kernel<<<BATCH * 64, 256>>>(out);
}

// round 15
// speedup vs baseline: 1.3422x; 1.2021x over previous
#include <cuda_runtime.h>
#include <cstdint>

#define L1LEN 512
#define L2LEN 512
#define DDIM  256
#define BATCH 2
#define NG    16
#define GS    16
#define TI    8
#define TJ    32           // source rows per tile
#define JSPLIT 2
#define NHALF (L2LEN / JSPLIT / TJ)   // 8 tiles per CTA
#define KSTR  260          // K tile row stride (floats) -> 4-phase LDS floor
#define NSTR  20           // sc2 inner stride
#define NTHR  256

__device__ float g_Q[BATCH * L1LEN * DDIM];
__device__ float g_K[BATCH * L2LEN * DDIM];
__device__ float g_V[BATCH * L2LEN * DDIM];
__device__ float g_pacc[BATCH * 64 * JSPLIT * TI * DDIM];
__device__ float g_pl[BATCH * 64 * JSPLIT * TI * NG];

// ---------------------------------------------------------------------------
// f32x2 packed helpers
// ---------------------------------------------------------------------------
__device__ __forceinline__ unsigned long long fma2u(unsigned long long a,
                                                    unsigned long long b,
                                                    unsigned long long c) {
    unsigned long long r;
    asm("fma.rn.f32x2 %0, %1, %2, %3;" : "=l"(r) : "l"(a), "l"(b), "l"(c));
    return r;
}

__device__ __forceinline__ void relu_fma(unsigned long long& acc,
                                         unsigned long long q2,
                                         unsigned long long nk2,
                                         unsigned long long w2) {
    asm("{\n\t"
        ".reg .b64 d;\n\t"
        ".reg .f32 lo, hi;\n\t"
        "add.rn.f32x2 d, %1, %2;\n\t"
        "mov.b64 {lo, hi}, d;\n\t"
        "max.f32 lo, lo, 0f00000000;\n\t"
        "max.f32 hi, hi, 0f00000000;\n\t"
        "mov.b64 d, {lo, hi};\n\t"
        "fma.rn.f32x2 %0, d, %3, %0;\n\t"
        "}"
        : "+l"(acc) : "l"(q2), "l"(nk2), "l"(w2));
}

__device__ __forceinline__ unsigned long long pk2(float a, float b) {
    unsigned long long r;
    asm("mov.b64 %0, {%1, %2};" : "=l"(r) : "f"(a), "f"(b));
    return r;
}

__device__ __forceinline__ float2 upk2(unsigned long long v) {
    float2 r;
    asm("mov.b64 {%0, %1}, %2;" : "=f"(r.x), "=f"(r.y) : "l"(v));
    return r;
}

// cp.async 16B + group ops
__device__ __forceinline__ void cp16(uint32_t dst, const void* src) {
    asm volatile("cp.async.cg.shared.global [%0], [%1], 16;"
                 :: "r"(dst), "l"(src));
}
__device__ __forceinline__ void cp_commit() {
    asm volatile("cp.async.commit_group;");
}
__device__ __forceinline__ void cp_wait0() {
    asm volatile("cp.async.wait_group 0;");
}

// ---------------------------------------------------------------------------
// QKV projection via tensor cores, 3xTF32 (R11 variant: 64x32, grid 384).
// ---------------------------------------------------------------------------
__device__ __forceinline__ uint32_t f2tf32(float f) {
    uint32_t r;
    asm("cvt.rna.tf32.f32 %0, %1;" : "=r"(r) : "f"(f));
    return r;
}

__device__ __forceinline__ void mma_tf32(float* c, const uint32_t* a,
                                         uint32_t b0, uint32_t b1) {
    asm("mma.sync.aligned.m16n8k8.row.col.f32.tf32.tf32.f32 "
        "{%0,%1,%2,%3}, {%4,%5,%6,%7}, {%8,%9}, {%0,%1,%2,%3};"
        : "+f"(c[0]), "+f"(c[1]), "+f"(c[2]), "+f"(c[3])
        : "r"(a[0]), "r"(a[1]), "r"(a[2]), "r"(a[3]), "r"(b0), "r"(b1));
}

__global__ __launch_bounds__(128) void qkv_gemm(const float* __restrict__ x_target,
                                                const float* __restrict__ x_source,
                                                const float* __restrict__ Wq,
                                                const float* __restrict__ Wk,
                                                const float* __restrict__ Wv) {
    const int z = blockIdx.z;
    const float* __restrict__ x = (z == 0) ? x_target : x_source;
    const float* __restrict__ W = (z == 0) ? Wq : ((z == 1) ? Wk : Wv);
    float* __restrict__ y       = (z == 0) ? g_Q : ((z == 1) ? g_K : g_V);

    __shared__ float    xs[64][36];
    __shared__ uint32_t wsh[32][36];
    __shared__ uint32_t wsl[32][36];

    const int t    = threadIdx.x;
    const int warp = t >> 5;
    const int lane = t & 31;
    const int gid  = lane >> 2;
    const int tig  = lane & 3;
    const int m_blk = blockIdx.x * 64;
    const int n_blk = blockIdx.y * 32;

    float acc[4][4] = {};

    for (int chunk = 0; chunk < 8; chunk++) {
        const int kc = chunk * 32;
        __syncthreads();
#pragma unroll
        for (int i = 0; i < 4; i++) {
            int idx = t + i * 128;
            int row = idx >> 3, col = (idx & 7) * 4;
            *(float4*)&xs[row][col] =
                *(const float4*)&x[(m_blk + row) * DDIM + kc + col];
        }
#pragma unroll
        for (int i = 0; i < 2; i++) {
            int idx = t + i * 128;
            int row = idx >> 3, col = (idx & 7) * 4;
            float4 wv = *(const float4*)&W[(n_blk + row) * DDIM + kc + col];
            uint32_t h0 = f2tf32(wv.x), h1 = f2tf32(wv.y);
            uint32_t h2 = f2tf32(wv.z), h3 = f2tf32(wv.w);
            wsh[row][col + 0] = h0; wsh[row][col + 1] = h1;
            wsh[row][col + 2] = h2; wsh[row][col + 3] = h3;
            wsl[row][col + 0] = f2tf32(wv.x - __uint_as_float(h0));
            wsl[row][col + 1] = f2tf32(wv.y - __uint_as_float(h1));
            wsl[row][col + 2] = f2tf32(wv.z - __uint_as_float(h2));
            wsl[row][col + 3] = f2tf32(wv.w - __uint_as_float(h3));
        }
        __syncthreads();

#pragma unroll
        for (int ks = 0; ks < 4; ks++) {
            const int k0 = ks * 8;
            float af[4];
            af[0] = xs[warp * 16 + gid][k0 + tig];
            af[1] = xs[warp * 16 + gid + 8][k0 + tig];
            af[2] = xs[warp * 16 + gid][k0 + tig + 4];
            af[3] = xs[warp * 16 + gid + 8][k0 + tig + 4];
            uint32_t ahi[4], alo[4];
#pragma unroll
            for (int j = 0; j < 4; j++) {
                ahi[j] = f2tf32(af[j]);
                alo[j] = f2tf32(af[j] - __uint_as_float(ahi[j]));
            }
#pragma unroll
            for (int nb = 0; nb < 4; nb++) {
                uint32_t bhi0 = wsh[nb * 8 + gid][k0 + tig];
                uint32_t bhi1 = wsh[nb * 8 + gid][k0 + tig + 4];
                uint32_t blo0 = wsl[nb * 8 + gid][k0 + tig];
                uint32_t blo1 = wsl[nb * 8 + gid][k0 + tig + 4];
                mma_tf32(acc[nb], ahi, bhi0, bhi1);
                mma_tf32(acc[nb], ahi, blo0, blo1);
                mma_tf32(acc[nb], alo, bhi0, bhi1);
            }
        }
    }

    const int m = m_blk + warp * 16 + gid;
#pragma unroll
    for (int nb = 0; nb < 4; nb++) {
        const int n = n_blk + nb * 8 + 2 * tig;
        *(float2*)&y[m * DDIM + n]       = make_float2(acc[nb][0], acc[nb][1]);
        *(float2*)&y[(m + 8) * DDIM + n] = make_float2(acc[nb][2], acc[nb][3]);
    }
}

// ---------------------------------------------------------------------------
// Fused attention, f32x2 math, 2-way j-split, no-max softmax.
// K: cp.async double-buffered smem (coalesced loads, 4-phase LDS reads).
// V: direct coalesced LDG from gmem in phase D (L2/L1-resident).
// 256 threads, 2 CTAs/SM. Grid 256 = BATCH * 64 * 2.
// ---------------------------------------------------------------------------
__global__ __launch_bounds__(NTHR, 2) void attn_kernel(const float* __restrict__ wmlp,
                                                       const float* __restrict__ bmlp) {
    extern __shared__ float sm[];
    float* q    = sm;                       // 2048 floats
    float* kbuf = q + TI * DDIM;            // 2 x 32*260 = 16640 floats
    float* sc2  = kbuf + 2 * TJ * KSTR;     // 5120 floats [(i*TJ+j)*NSTR + n]

    const int t     = threadIdx.x;
    const int bx    = blockIdx.x;
    const int b     = bx >> 7;
    const int itile = (bx >> 1) & 63;
    const int jh2   = bx & 1;               // j half of L2 (256 rows)
    const int i_base = itile * TI;
    const int part   = bx;

    const int jj = t & 31;
    const int nc = t >> 5;                  // groups 2nc, 2nc+1
    const int qp = t & 31;
    const int ih = (t >> 5) & 1;
    const int jq = t >> 6;
    const int n0 = (4 * qp) & 15;

    const float b0 = bmlp[0];
    unsigned long long w2[8];
#pragma unroll
    for (int p = 0; p < 8; p++) w2[p] = pk2(wmlp[2 * p], wmlp[2 * p + 1]);

    {
        const float* Qg = g_Q + (b * L1LEN + i_base) * DDIM;
#pragma unroll
        for (int it = 0; it < 2; it++) {
            int idx = t + it * NTHR;
            int row = idx >> 6, col = (idx & 63) * 4;
            *(float4*)&q[row * DDIM + col] = *(const float4*)&Qg[row * DDIM + col];
        }
    }

    const float* Kg = g_K + (b * L2LEN + jh2 * (L2LEN / JSPLIT)) * DDIM;
    const float* Vg = g_V + (b * L2LEN + jh2 * (L2LEN / JSPLIT)) * DDIM;

    // prologue: prefetch K tile 0 into kbuf[0] (coalesced cp.async)
    {
        uint32_t dst = (uint32_t)__cvta_generic_to_shared(kbuf);
#pragma unroll
        for (int it = 0; it < (TJ * DDIM / 4) / NTHR; it++) {
            int idx = t + it * NTHR;
            int row = idx >> 6, col = (idx & 63) * 4;
            cp16(dst + (row * KSTR + col) * 4, &Kg[row * DDIM + col]);
        }
        cp_commit();
    }

    ulonglong2 acc2[4][2];
#pragma unroll
    for (int r = 0; r < 4; r++) {
        acc2[r][0].x = 0ull; acc2[r][0].y = 0ull;
        acc2[r][1].x = 0ull; acc2[r][1].y = 0ull;
    }
    float lsum = 0.f;

    for (int tile = 0; tile < NHALF; tile++) {
        cp_wait0();        // K(tile) landed (thread-local)
        __syncthreads();   // publish K(tile); prev D done with sc2

        // prefetch K(tile+1) into the other buffer (overlaps B + D)
        if (tile + 1 < NHALF) {
            const float* Kn = Kg + (tile + 1) * TJ * DDIM;
            uint32_t dst = (uint32_t)__cvta_generic_to_shared(
                kbuf + ((tile + 1) & 1) * TJ * KSTR);
#pragma unroll
            for (int it = 0; it < (TJ * DDIM / 4) / NTHR; it++) {
                int idx = t + it * NTHR;
                int row = idx >> 6, col = (idx & 63) * 4;
                cp16(dst + (row * KSTR + col) * 4, &Kn[row * DDIM + col]);
            }
            cp_commit();
        }

        const float* kt = kbuf + (tile & 1) * TJ * KSTR;

        // ---- Phase B: packed scores + exp -> sc2 (K from smem, Q broadcast)
#pragma unroll
        for (int n2 = 0; n2 < 2; n2++) {
            const int n = nc * 2 + n2;
            const float* kr = kt + jj * KSTR + n * GS;
            unsigned long long nk2[8];
#pragma unroll
            for (int dq = 0; dq < 4; dq++) {
                float4 kq = *(const float4*)&kr[dq * 4];
                nk2[dq * 2]     = pk2(-kq.x, -kq.y);
                nk2[dq * 2 + 1] = pk2(-kq.z, -kq.w);
            }
            unsigned long long s2[8];
#pragma unroll
            for (int i = 0; i < 8; i++) s2[i] = 0ull;
#pragma unroll
            for (int dq = 0; dq < 4; dq++) {
#pragma unroll
                for (int i = 0; i < 8; i++) {
                    const ulonglong2 qv =
                        *(const ulonglong2*)&q[i * DDIM + n * GS + dq * 4];
                    relu_fma(s2[i], qv.x, nk2[dq * 2], w2[dq * 2]);
                    relu_fma(s2[i], qv.y, nk2[dq * 2 + 1], w2[dq * 2 + 1]);
                }
            }
#pragma unroll
            for (int i = 0; i < 8; i++) {
                float2 f = upk2(s2[i]);
                sc2[(i * TJ + jj) * NSTR + n] =
                    __expf(fmaxf(f.x + f.y + b0, 0.f));
            }
        }
        __syncthreads();   // sc2 visible

        // ---- exp-sum (t<128, overlaps with D)
        if (t < TI * NG) {
            const int ci = t >> 4, cn = t & 15;
            const float* base = sc2 + ci * TJ * NSTR + cn;
            float s0 = 0.f, s1 = 0.f;
#pragma unroll
            for (int j = 0; j < TJ; j += 2) {
                s0 += base[j * NSTR];
                s1 += base[(j + 1) * NSTR];
            }
            lsum += s0 + s1;
        }

        // ---- Phase D: warp (ih,jq): 4 i x 8 j; V direct from gmem (coalesced)
        {
            const int j0 = jq * 8;
            const float* Vt = Vg + tile * TJ * DDIM;
#pragma unroll
            for (int jo = 0; jo < 8; jo++) {
                const int j = j0 + jo;
                const ulonglong2 v0 =
                    *(const ulonglong2*)&Vt[j * DDIM + 4 * qp];
                const ulonglong2 v1 =
                    *(const ulonglong2*)&Vt[j * DDIM + 4 * qp + 128];
#pragma unroll
                for (int r = 0; r < 4; r++) {
                    const ulonglong2 p = *(const ulonglong2*)
                        &sc2[((4 * ih + r) * TJ + j) * NSTR + n0];
                    acc2[r][0].x = fma2u(p.x, v0.x, acc2[r][0].x);
                    acc2[r][0].y = fma2u(p.y, v0.y, acc2[r][0].y);
                    acc2[r][1].x = fma2u(p.x, v1.x, acc2[r][1].x);
                    acc2[r][1].y = fma2u(p.y, v1.y, acc2[r][1].y);
                }
            }
        }
    }

    // ---- reduce jq partials via kbuf scratch, write partials to global
    __syncthreads();
    {
        float* scr = kbuf;
        int base = (t >> 5) * 1024 + qp * 32;
#pragma unroll
        for (int r = 0; r < 4; r++) {
            *(float4*)&scr[base + r * 8]     = *(float4*)&acc2[r][0];
            *(float4*)&scr[base + r * 8 + 4] = *(float4*)&acc2[r][1];
        }
    }
    __syncthreads();
    {
        const int i   = t >> 5;
        const int mih = i >> 2, r = i & 3;
        const float* scr = kbuf;
        float4 s0 = make_float4(0.f, 0.f, 0.f, 0.f);
        float4 s1 = make_float4(0.f, 0.f, 0.f, 0.f);
#pragma unroll
        for (int jqq = 0; jqq < 4; jqq++) {
            const int wv = mih + 2 * jqq;
            const float* pbase = scr + wv * 1024 + (t & 31) * 32 + r * 8;
            float4 a0 = *(const float4*)&pbase[0];
            float4 a1 = *(const float4*)&pbase[4];
            s0.x += a0.x; s0.y += a0.y; s0.z += a0.z; s0.w += a0.w;
            s1.x += a1.x; s1.y += a1.y; s1.z += a1.z; s1.w += a1.w;
        }
        float* pb = g_pacc + part * (TI * DDIM);
        *(float4*)&pb[i * DDIM + 4 * (t & 31)]       = s0;
        *(float4*)&pb[i * DDIM + 4 * (t & 31) + 128] = s1;
    }
    if (t < TI * NG) g_pl[part * (TI * NG) + t] = lsum;
}

// ---------------------------------------------------------------------------
// Merge: out = (acc0 + acc1) / (l0 + l1)
// ---------------------------------------------------------------------------
__global__ __launch_bounds__(256) void merge_kernel(float* __restrict__ out) {
    const int bx = blockIdx.x;
    const int t  = threadIdx.x;
    const int p0 = bx * 2, p1 = bx * 2 + 1;
    const float* a0 = g_pacc + p0 * (TI * DDIM);
    const float* a1 = g_pacc + p1 * (TI * DDIM);
    const float* l0 = g_pl + p0 * (TI * NG);
    const float* l1 = g_pl + p1 * (TI * NG);
    float* ob = out + bx * (TI * DDIM);

#pragma unroll
    for (int k = 0; k < 2; k++) {
        int idx = t + k * 256;
        int i   = idx >> 6;
        int d0  = (idx & 63) * 4;
        int nq  = d0 & 15;
        float4 x0 = *(const float4*)&a0[i * DDIM + d0];
        float4 x1 = *(const float4*)&a1[i * DDIM + d0];
        float4 u0 = *(const float4*)&l0[i * NG + nq];
        float4 u1 = *(const float4*)&l1[i * NG + nq];
        float4 r;
        r.x = (x0.x + x1.x) / (u0.x + u1.x);
        r.y = (x0.y + x1.y) / (u0.y + u1.y);
        r.z = (x0.z + x1.z) / (u0.z + u1.z);
        r.w = (x0.w + x1.w) / (u0.w + u1.w);
        *(float4*)&ob[i * DDIM + d0] = r;
    }
}

// ---------------------------------------------------------------------------
extern "C" void kernel_launch(void* const* d_in, const int* in_sizes, int n_in,
                              void* d_out, int out_size) {
    const float* x_source = (const float*)d_in[0];
    const float* x_target = (const float*)d_in[1];
    const float* Wq       = (const float*)d_in[2];
    const float* Wk       = (const float*)d_in[3];
    const float* Wv       = (const float*)d_in[4];
    const float* w_mlp    = (const float*)d_in[5];
    const float* b_mlp    = (const float*)d_in[6];
    float* out            = (float*)d_out;

    dim3 ggrid(16, 8, 3);
    qkv_gemm<<<ggrid, 128>>>(x_target, x_source, Wq, Wk, Wv);

    const size_t smem_bytes =
        (TI * DDIM + 2 * TJ * KSTR + TI * TJ * NSTR) * sizeof(float);
    cudaFuncSetAttribute(attn_kernel, cudaFuncAttributeMaxDynamicSharedMemorySize,
                         (int)smem_bytes);
    attn_kernel<<<BATCH * 64 * JSPLIT, NTHR, smem_bytes>>>(w_mlp, b_mlp);

    merge_kernel<<<BATCH * 64, 256>>>(out);
}